// round 2
// baseline (speedup 1.0000x reference)
#include <cuda_runtime.h>
#include <math.h>

// Problem shape (fixed by setup_inputs): pred/target (32,1,1024,1024) f32.
#define Wd   1024
#define Hd   1024
#define Bd   32
#define RPB  16                       // rows per block
#define GRPS (Hd / RPB)               // 64 row-groups per image
#define NBLK (Bd * GRPS)              // 2048 blocks
#define NTHR 256                      // 256 threads * 4 cols = 1024 cols

#define BW 3.0f                       // boundary weight
#define NEG_BIG (-1.0e30f)
#define POS_BIG ( 1.0e30f)

__device__ float g_partials[NBLK];

__global__ __launch_bounds__(NTHR)
void bab_main(const float* __restrict__ pred, const float* __restrict__ target)
{
    // +8 pad: logical column x lives at sbuf[4 + x]; halo slots at logical
    // [-1] and [Wd]; base of column 0 is 16B-aligned for float4 stores.
    __shared__ __align__(16) float sMaxBuf[Wd + 8];
    __shared__ __align__(16) float sMinBuf[Wd + 8];
    float* sMax = sMaxBuf + 4;   // sMax[x] valid for x in [-1, Wd]
    float* sMin = sMinBuf + 4;

    const int tid = threadIdx.x;
    const int grp = blockIdx.x;
    const int img = grp / GRPS;
    const int y0  = (grp % GRPS) * RPB;
    const int x0  = tid * 4;

    const float* __restrict__ tb = target + (size_t)img * Hd * Wd;
    const float* __restrict__ pb = pred   + (size_t)img * Hd * Wd;

    if (tid == 0) {
        sMax[-1] = NEG_BIG; sMax[Wd] = NEG_BIG;   // max identity at image border
        sMin[-1] = POS_BIG; sMin[Wd] = POS_BIG;   // min identity at image border
    }

    // Rolling 3-row register window of target (float4 per thread).
    float4 cur  = *(const float4*)(tb + (size_t)y0 * Wd + x0);
    float4 prev = (y0 > 0) ? *(const float4*)(tb + (size_t)(y0 - 1) * Wd + x0) : cur;

    float acc = 0.0f;

    #pragma unroll 4
    for (int r = 0; r < RPB; ++r) {
        const int y = y0 + r;
        float4 next = (y < Hd - 1) ? *(const float4*)(tb + (size_t)(y + 1) * Wd + x0) : cur;

        // Vertical 3-tap extremes (missing border rows replaced by cur => identity).
        float4 vmax, vmin;
        vmax.x = fmaxf(fmaxf(prev.x, cur.x), next.x);
        vmax.y = fmaxf(fmaxf(prev.y, cur.y), next.y);
        vmax.z = fmaxf(fmaxf(prev.z, cur.z), next.z);
        vmax.w = fmaxf(fmaxf(prev.w, cur.w), next.w);
        vmin.x = fminf(fminf(prev.x, cur.x), next.x);
        vmin.y = fminf(fminf(prev.y, cur.y), next.y);
        vmin.z = fminf(fminf(prev.z, cur.z), next.z);
        vmin.w = fminf(fminf(prev.w, cur.w), next.w);

        __syncthreads();                       // prior-iteration shared reads done (WAR)
        *(float4*)(sMax + x0) = vmax;
        *(float4*)(sMin + x0) = vmin;
        __syncthreads();                       // extreme rows visible (RAW)

        // Pred row (coalesced float4) + horizontal 3-tap from shared.
        const float4 p = *(const float4*)(pb + (size_t)y * Wd + x0);

        float tv[4] = { cur.x, cur.y, cur.z, cur.w };
        float pv[4] = { p.x, p.y, p.z, p.w };

        #pragma unroll
        for (int i = 0; i < 4; ++i) {
            const int x = x0 + i;
            const float dmax = fmaxf(fmaxf(sMax[x - 1], sMax[x]), sMax[x + 1]);
            const float dmin = fminf(fminf(sMin[x - 1], sMin[x]), sMin[x + 1]);
            const float w    = (dmax - dmin > 0.5f) ? BW : 1.0f;
            const float t    = tv[i];
            const float pc   = pv[i];
            // t is exactly 0 or 1 -> BCE collapses to a select.
            const float l = (t > 0.5f) ? (-__logf(pc))
                                       : (-__logf(fmaxf(1.0f - pc, 1.0e-30f)));
            acc = fmaf(w, l, acc);
        }

        prev = cur;
        cur  = next;
    }

    // Block reduction: warp shuffle then cross-warp via shared.
    #pragma unroll
    for (int off = 16; off > 0; off >>= 1)
        acc += __shfl_down_sync(0xFFFFFFFFu, acc, off);

    __shared__ float swarp[NTHR / 32];
    if ((tid & 31) == 0) swarp[tid >> 5] = acc;
    __syncthreads();
    if (tid < (NTHR / 32)) {
        float v = swarp[tid];
        #pragma unroll
        for (int off = (NTHR / 64); off > 0; off >>= 1)
            v += __shfl_down_sync(0xFFu, v, off);
        if (tid == 0) g_partials[blockIdx.x] = v;
    }
}

__global__ __launch_bounds__(256)
void bab_reduce(float* __restrict__ out)
{
    __shared__ double sd[256];
    double s = 0.0;
    for (int i = threadIdx.x; i < NBLK; i += 256)
        s += (double)g_partials[i];
    sd[threadIdx.x] = s;
    __syncthreads();
    for (int stride = 128; stride > 0; stride >>= 1) {
        if (threadIdx.x < stride) sd[threadIdx.x] += sd[threadIdx.x + stride];
        __syncthreads();
    }
    if (threadIdx.x == 0)
        out[0] = (float)(sd[0] / (double)((size_t)Bd * Hd * Wd));
}

extern "C" void kernel_launch(void* const* d_in, const int* in_sizes, int n_in,
                              void* d_out, int out_size)
{
    (void)in_sizes; (void)n_in; (void)out_size;
    const float* pred   = (const float*)d_in[0];
    const float* target = (const float*)d_in[1];
    float* out = (float*)d_out;

    bab_main<<<NBLK, NTHR>>>(pred, target);
    bab_reduce<<<1, 256>>>(out);
}

// round 3
// speedup vs baseline: 1.4581x; 1.4581x over previous
#include <cuda_runtime.h>
#include <math.h>

// Problem shape (fixed by setup_inputs): pred/target (32,1,1024,1024) f32.
#define Wd   1024
#define Hd   1024
#define Bd   32
#define RPB  32                       // rows per block
#define GRPS (Hd / RPB)               // 32 row-groups per image
#define NBLK (Bd * GRPS)              // 1024 blocks
#define NTHR 256                      // 8 warps * 128 cols = 1024 cols

#define BW 3.0f                       // boundary weight
#define NEG_BIG (-1.0e30f)
#define POS_BIG ( 1.0e30f)
#define FULLM 0xFFFFFFFFu

__device__ float        g_partials[NBLK];
__device__ unsigned int g_ticket;     // zero-initialized; reset by last block

__device__ __forceinline__ float max3(float a, float b, float c) {
    return fmaxf(fmaxf(a, b), c);
}
__device__ __forceinline__ float min3(float a, float b, float c) {
    return fminf(fminf(a, b), c);
}

__global__ __launch_bounds__(NTHR)
void bab_fused(const float* __restrict__ pred, const float* __restrict__ target,
               float* __restrict__ out)
{
    const int tid  = threadIdx.x;
    const int lane = tid & 31;
    const int warp = tid >> 5;

    const int grp = blockIdx.x;
    const int img = grp / GRPS;
    const int y0  = (grp % GRPS) * RPB;

    const int x0 = warp * 128 + lane * 4;     // this thread's 4 columns
    const int xL = warp * 128 - 1;            // halo col (lane 0 only)
    const int xR = warp * 128 + 128;          // halo col (lane 31 only)
    const bool doL = (lane == 0)  && (xL >= 0);
    const bool doR = (lane == 31) && (xR < Wd);

    const float* __restrict__ tb = target + (size_t)img * Hd * Wd;
    const float* __restrict__ pb = pred   + (size_t)img * Hd * Wd;

    // Rolling 3-row register window of target (float4 per thread) +
    // rolling scalar halo windows on the edge lanes.
    float4 cur  = *(const float4*)(tb + (size_t)y0 * Wd + x0);
    float4 prev = (y0 > 0) ? *(const float4*)(tb + (size_t)(y0 - 1) * Wd + x0) : cur;

    float curL = 0.f, prevL = 0.f, curR = 0.f, prevR = 0.f;
    if (doL) { curL = tb[(size_t)y0 * Wd + xL];
               prevL = (y0 > 0) ? tb[(size_t)(y0 - 1) * Wd + xL] : curL; }
    if (doR) { curR = tb[(size_t)y0 * Wd + xR];
               prevR = (y0 > 0) ? tb[(size_t)(y0 - 1) * Wd + xR] : curR; }

    float acc = 0.0f;

    #pragma unroll 4
    for (int r = 0; r < RPB; ++r) {
        const int y = y0 + r;
        const bool hasNext = (y < Hd - 1);

        float4 next = hasNext ? *(const float4*)(tb + (size_t)(y + 1) * Wd + x0) : cur;
        float nextL = doL ? (hasNext ? tb[(size_t)(y + 1) * Wd + xL] : curL) : 0.f;
        float nextR = doR ? (hasNext ? tb[(size_t)(y + 1) * Wd + xR] : curR) : 0.f;

        // Vertical 3-tap extremes (border rows replaced by cur => identity).
        float4 vmax, vmin;
        vmax.x = max3(prev.x, cur.x, next.x);
        vmax.y = max3(prev.y, cur.y, next.y);
        vmax.z = max3(prev.z, cur.z, next.z);
        vmax.w = max3(prev.w, cur.w, next.w);
        vmin.x = min3(prev.x, cur.x, next.x);
        vmin.y = min3(prev.y, cur.y, next.y);
        vmin.z = min3(prev.z, cur.z, next.z);
        vmin.w = min3(prev.w, cur.w, next.w);

        // Neighbor-column extremes via warp shuffle (lane +/- 1).
        float lMax = __shfl_up_sync(FULLM, vmax.w, 1);
        float lMin = __shfl_up_sync(FULLM, vmin.w, 1);
        float rMax = __shfl_down_sync(FULLM, vmax.x, 1);
        float rMin = __shfl_down_sync(FULLM, vmin.x, 1);

        if (lane == 0) {
            if (doL) { lMax = max3(prevL, curL, nextL);
                       lMin = min3(prevL, curL, nextL); }
            else     { lMax = NEG_BIG; lMin = POS_BIG; }   // image left border
        }
        if (lane == 31) {
            if (doR) { rMax = max3(prevR, curR, nextR);
                       rMin = min3(prevR, curR, nextR); }
            else     { rMax = NEG_BIG; rMin = POS_BIG; }   // image right border
        }

        // Horizontal 3-tap: dilated/eroded per column, then weight + BCE.
        const float4 p = *(const float4*)(pb + (size_t)y * Wd + x0);

        float d0 = max3(lMax,   vmax.x, vmax.y), e0 = min3(lMin,   vmin.x, vmin.y);
        float d1 = max3(vmax.x, vmax.y, vmax.z), e1 = min3(vmin.x, vmin.y, vmin.z);
        float d2 = max3(vmax.y, vmax.z, vmax.w), e2 = min3(vmin.y, vmin.z, vmin.w);
        float d3 = max3(vmax.z, vmax.w, rMax),   e3 = min3(vmin.z, vmin.w, rMin);

        float w0 = (d0 - e0 > 0.5f) ? BW : 1.0f;
        float w1 = (d1 - e1 > 0.5f) ? BW : 1.0f;
        float w2 = (d2 - e2 > 0.5f) ? BW : 1.0f;
        float w3 = (d3 - e3 > 0.5f) ? BW : 1.0f;

        // target is exactly 0 or 1 -> BCE collapses to a select of one log.
        float l0 = (cur.x > 0.5f) ? (-__logf(p.x)) : (-__logf(fmaxf(1.0f - p.x, 1e-30f)));
        float l1 = (cur.y > 0.5f) ? (-__logf(p.y)) : (-__logf(fmaxf(1.0f - p.y, 1e-30f)));
        float l2 = (cur.z > 0.5f) ? (-__logf(p.z)) : (-__logf(fmaxf(1.0f - p.z, 1e-30f)));
        float l3 = (cur.w > 0.5f) ? (-__logf(p.w)) : (-__logf(fmaxf(1.0f - p.w, 1e-30f)));

        acc = fmaf(w0, l0, acc);
        acc = fmaf(w1, l1, acc);
        acc = fmaf(w2, l2, acc);
        acc = fmaf(w3, l3, acc);

        prev = cur;  cur  = next;
        prevL = curL; curL = nextL;
        prevR = curR; curR = nextR;
    }

    // ---- Block reduction: warp shuffle, then cross-warp via shared. ----
    #pragma unroll
    for (int off = 16; off > 0; off >>= 1)
        acc += __shfl_down_sync(FULLM, acc, off);

    __shared__ float swarp[NTHR / 32];
    if (lane == 0) swarp[warp] = acc;
    __syncthreads();
    if (tid == 0) {
        float v = 0.0f;
        #pragma unroll
        for (int i = 0; i < NTHR / 32; ++i) v += swarp[i];
        g_partials[blockIdx.x] = v;
    }

    // ---- Last-block fused finalize (deterministic order). ----
    __shared__ bool s_last;
    __threadfence();
    if (tid == 0) {
        unsigned int old = atomicAdd(&g_ticket, 1u);
        s_last = (old == NBLK - 1);
    }
    __syncthreads();

    if (s_last) {
        __shared__ double sd[NTHR];
        double s = 0.0;
        for (int i = tid; i < NBLK; i += NTHR)   // fixed order per thread
            s += (double)g_partials[i];
        sd[tid] = s;
        __syncthreads();
        #pragma unroll
        for (int stride = NTHR / 2; stride > 0; stride >>= 1) {
            if (tid < stride) sd[tid] += sd[tid + stride];
            __syncthreads();
        }
        if (tid == 0) {
            out[0] = (float)(sd[0] / (double)((size_t)Bd * Hd * Wd));
            g_ticket = 0;                        // reset for next launch/replay
        }
    }
}

extern "C" void kernel_launch(void* const* d_in, const int* in_sizes, int n_in,
                              void* d_out, int out_size)
{
    (void)in_sizes; (void)n_in; (void)out_size;
    const float* pred   = (const float*)d_in[0];
    const float* target = (const float*)d_in[1];
    float* out = (float*)d_out;

    bab_fused<<<NBLK, NTHR>>>(pred, target, out);
}